// round 14
// baseline (speedup 1.0000x reference)
#include <cuda_runtime.h>
#include <cuda_bf16.h>
#include <cuda_fp16.h>
#include <cstdint>

// LuongAttention B=16, TQ=2048, TK=2048, D=1024
// out = [context (B*TQ*D fp32) | alignment (B*TQ*TK fp32)]
static constexpr int Bsz = 16;
static constexpr int TQ  = 2048;
static constexpr int TK  = 2048;
static constexpr int D   = 1024;

static constexpr int PERSIST_GRID = 304;   // 2 CTAs x 152 SMs (GB300)

// ---------------- device scratch (allocation-free, 16B aligned) ----------------
__device__ __align__(16) __nv_bfloat16 g_dec_h[(size_t)Bsz * TQ * D];
__device__ __align__(16) __nv_bfloat16 g_dec_l[(size_t)Bsz * TQ * D];
__device__ __align__(16) __nv_bfloat16 g_enc_h[(size_t)Bsz * TK * D];
__device__ __align__(16) __nv_bfloat16 g_enc_l[(size_t)Bsz * TK * D];
__device__ __align__(16) __half        g_encT_h[(size_t)Bsz * D * TK];   // fp16 (single)
__device__ __align__(16) __nv_bfloat16 g_Wt_h[(size_t)D * D];
__device__ __align__(16) __nv_bfloat16 g_Wt_l[(size_t)D * D];
__device__ __align__(16) __nv_bfloat16 g_key_h[(size_t)Bsz * TK * D];
__device__ __align__(16) __nv_bfloat16 g_key_l[(size_t)Bsz * TK * D];
__device__ __align__(16) __half        g_al_f16[(size_t)Bsz * TQ * TK];  // fp16 alignment

// ---------------- helpers ----------------
__device__ __forceinline__ uint32_t smem_u32(const void* p) {
    uint32_t a;
    asm("{ .reg .u64 t; cvta.to.shared.u64 t, %1; cvt.u32.u64 %0, t; }"
        : "=r"(a) : "l"(p));
    return a;
}
__device__ __forceinline__ void cp_async16(uint32_t dst, const void* src) {
    asm volatile("{ .reg .u64 g; cvta.to.global.u64 g, %1;"
                 "  cp.async.cg.shared.global [%0], [g], 16; }"
                 :: "r"(dst), "l"(src) : "memory");
}
#define CP_COMMIT() asm volatile("cp.async.commit_group;" ::: "memory")
#define CP_WAIT1()  asm volatile("cp.async.wait_group 1;" ::: "memory")
#define CP_WAIT0()  asm volatile("cp.async.wait_group 0;" ::: "memory")

__device__ __forceinline__ void ldm_x4(uint32_t* r, uint32_t addr) {
    asm volatile("ldmatrix.sync.aligned.m8n8.x4.shared.b16 {%0,%1,%2,%3}, [%4];"
                 : "=r"(r[0]), "=r"(r[1]), "=r"(r[2]), "=r"(r[3]) : "r"(addr));
}
__device__ __forceinline__ void mma_bf16(float* c, const uint32_t* a, const uint32_t* b) {
    asm volatile("mma.sync.aligned.m16n8k16.row.col.f32.bf16.bf16.f32 "
                 "{%0,%1,%2,%3}, {%4,%5,%6,%7}, {%8,%9}, {%0,%1,%2,%3};"
                 : "+f"(c[0]), "+f"(c[1]), "+f"(c[2]), "+f"(c[3])
                 : "r"(a[0]), "r"(a[1]), "r"(a[2]), "r"(a[3]), "r"(b[0]), "r"(b[1]));
}
__device__ __forceinline__ void mma_fp16(float* c, const uint32_t* a, const uint32_t* b) {
    asm volatile("mma.sync.aligned.m16n8k16.row.col.f32.f16.f16.f32 "
                 "{%0,%1,%2,%3}, {%4,%5,%6,%7}, {%8,%9}, {%0,%1,%2,%3};"
                 : "+f"(c[0]), "+f"(c[1]), "+f"(c[2]), "+f"(c[3])
                 : "r"(a[0]), "r"(a[1]), "r"(a[2]), "r"(a[3]), "r"(b[0]), "r"(b[1]));
}
__device__ __forceinline__ void split2(float x, __nv_bfloat16& h, __nv_bfloat16& l) {
    h = __float2bfloat16_rn(x);
    l = __float2bfloat16_rn(x - __bfloat162float(h));
}

// smem geometry: 128 rows x 64B (32 elems), XOR swizzle -> no padding
static constexpr int TILE_B  = 128 * 64;        // 8192 B per tile array
static constexpr int STAGE_B = 4 * TILE_B;      // Ah,Al,Bh,Bl = 32768 B
static constexpr int NSTAGE  = 3;
static constexpr int SMEM_DYN = NSTAGE * STAGE_B;  // 98304 B

static constexpr int CTX_STAGE_B = 2 * TILE_B;     // A,B = 16384 B
static constexpr int CTX_SMEM    = NSTAGE * CTX_STAGE_B;  // 49152 B

__device__ __forceinline__ uint32_t sw_addr(int row, int chunk) {
    return (uint32_t)(row * 64 + ((chunk ^ ((row >> 1) & 3)) << 4));
}

// ---------------------------------------------------------------------------
// Persistent bf16x3 GEMM (emulated fp32):  C[M,N] = A[M,K] * B[N,K]^T
// Tile 128x128, BK=32, 128 thr (4 warps, 2Mx2N, warp tile 64x64)
// Linearized 3-stage pipeline that NEVER drains across tile boundaries;
// epilogue overlaps next tile's in-flight cp.async loads.
// Tile t -> bz = t/ntXY, by = (t%ntXY)/ntX, bx = t%ntX.
// ---------------------------------------------------------------------------
__global__ __launch_bounds__(128, 2)
void gemm_bf16x3(const __nv_bfloat16* __restrict__ Ah, const __nv_bfloat16* __restrict__ Al,
                 const __nv_bfloat16* __restrict__ Bh, const __nv_bfloat16* __restrict__ Bl,
                 float* __restrict__ Cf,
                 __nv_bfloat16* __restrict__ Chi, __nv_bfloat16* __restrict__ Clo,
                 const float* __restrict__ bias,
                 int K, int ldC,
                 long long sA, long long sB, long long sC,
                 int ntX, int ntXY, int ntiles)
{
    extern __shared__ __align__(128) char sm[];
    const uint32_t s0 = smem_u32(sm);

    const int bid = (int)blockIdx.x;
    if (bid >= ntiles) return;
    const int gsz = (int)gridDim.x;
    const int nk  = K >> 5;
    const int myN = (ntiles - 1 - bid) / gsz + 1;
    const int total = myN * nk;

    const int tid  = threadIdx.x;
    const int wid  = tid >> 5;
    const int lane = tid & 31;
    const int wm   = wid & 1;
    const int wn   = wid >> 1;

    const int lr0 = tid >> 2;
    const int lc  = tid & 3;

    // ---- load-side tile state ----
    int lt = bid, lk = 0;
    const __nv_bfloat16 *lAh, *lAl, *lBh, *lBl;
    auto setLoadTile = [&](int t) {
        int bz = t / ntXY; int rr = t - bz * ntXY;
        int by = rr / ntX; int bx = rr - by * ntX;
        long long zA = (long long)bz * sA + (long long)(by << 7) * K;
        long long zB = (long long)bz * sB + (long long)(bx << 7) * K;
        lAh = Ah + zA; lAl = Al + zA; lBh = Bh + zB; lBl = Bl + zB;
    };
    setLoadTile(lt);

    auto tileLoad = [&](int stage) {
        const uint32_t db = s0 + stage * STAGE_B;
        const int k0 = lk << 5;
#pragma unroll
        for (int i = 0; i < 4; ++i) {
            const int r = lr0 + i * 32;
            const uint32_t so = sw_addr(r, lc);
            const long long go = (long long)r * K + k0 + lc * 8;
            cp_async16(db + 0 * TILE_B + so, lAh + go);
            cp_async16(db + 1 * TILE_B + so, lAl + go);
            cp_async16(db + 2 * TILE_B + so, lBh + go);
            cp_async16(db + 3 * TILE_B + so, lBl + go);
        }
        CP_COMMIT();
        if (++lk == nk) { lk = 0; lt += gsz; if (lt < ntiles) setLoadTile(lt); }
    };

    const int rowA0 = wm * 64 + (lane & 15);
    const int hiA   = lane >> 4;
    const int rowB0 = wn * 64 + (lane & 7) + ((lane & 16) >> 1);
    const int hiB   = (lane & 8) >> 3;

    float acc[4][8][4];
#pragma unroll
    for (int a = 0; a < 4; ++a)
#pragma unroll
        for (int b = 0; b < 8; ++b)
#pragma unroll
            for (int c = 0; c < 4; ++c) acc[a][b][c] = 0.0f;

    tileLoad(0);
    tileLoad(1);

    int cst = 0, lst = 2;       // compute / load stage (mod 3)
    int ct = bid, ck = 0;       // compute-side tile + k index

    for (int g = 0; g < total; ++g) {
        if (g + 2 < total) { CP_WAIT1(); } else { CP_WAIT0(); }
        __syncthreads();
        if (g + 2 < total) { tileLoad(lst); lst = (lst == 2) ? 0 : lst + 1; }

        const uint32_t sb = s0 + cst * STAGE_B;
        cst = (cst == 2) ? 0 : cst + 1;

#pragma unroll
        for (int ks = 0; ks < 2; ++ks) {
            uint32_t fAh[4][4], fAl[4][4];
#pragma unroll
            for (int mt = 0; mt < 4; ++mt) {
                const int r = rowA0 + mt * 16;
                const uint32_t ao = sw_addr(r, hiA + ks * 2);
                ldm_x4(fAh[mt], sb + 0 * TILE_B + ao);
                ldm_x4(fAl[mt], sb + 1 * TILE_B + ao);
            }
#pragma unroll
            for (int pp = 0; pp < 4; ++pp) {
                const int rb = rowB0 + pp * 16;
                const uint32_t bo = sw_addr(rb, hiB + ks * 2);
                uint32_t fBh[4], fBl[4];
                ldm_x4(fBh, sb + 2 * TILE_B + bo);
                ldm_x4(fBl, sb + 3 * TILE_B + bo);
#pragma unroll
                for (int q = 0; q < 2; ++q) {
                    const int nt = pp * 2 + q;
#pragma unroll
                    for (int mt = 0; mt < 4; ++mt)
                        mma_bf16(acc[mt][nt], fAh[mt], fBh + q * 2);
#pragma unroll
                    for (int mt = 0; mt < 4; ++mt)
                        mma_bf16(acc[mt][nt], fAh[mt], fBl + q * 2);
#pragma unroll
                    for (int mt = 0; mt < 4; ++mt)
                        mma_bf16(acc[mt][nt], fAl[mt], fBh + q * 2);
                }
            }
        }

        if (++ck == nk) {
            ck = 0;
            // ---------------- epilogue (overlaps next tile's loads) -------
            int bz = ct / ntXY; int rr = ct - bz * ntXY;
            int by = rr / ntX;  int bx = rr - by * ntX;
            const int rBase = (by << 7) + wm * 64 + (lane >> 2);
            const int cBase = (bx << 7) + wn * 64 + (lane & 3) * 2;
            const long long zC = (long long)bz * sC;
#pragma unroll
            for (int mt = 0; mt < 4; ++mt) {
#pragma unroll
                for (int h = 0; h < 2; ++h) {
                    const int row = rBase + mt * 16 + h * 8;
#pragma unroll
                    for (int nt = 0; nt < 8; ++nt) {
                        const int col = cBase + nt * 8;
                        float v0 = acc[mt][nt][h * 2 + 0];
                        float v1 = acc[mt][nt][h * 2 + 1];
                        if (bias) { v0 += bias[col]; v1 += bias[col + 1]; }
                        const long long o = zC + (long long)row * ldC + col;
                        if (Cf) {
                            float2 fv; fv.x = v0; fv.y = v1;
                            *(float2*)(Cf + o) = fv;
                        }
                        if (Chi) {
                            __nv_bfloat16 h0, l0, h1, l1;
                            split2(v0, h0, l0); split2(v1, h1, l1);
                            __nv_bfloat162 hv; hv.x = h0; hv.y = h1;
                            __nv_bfloat162 lv; lv.x = l0; lv.y = l1;
                            *(__nv_bfloat162*)(Chi + o) = hv;
                            *(__nv_bfloat162*)(Clo + o) = lv;
                        }
                    }
                }
            }
            ct += gsz;
#pragma unroll
            for (int a = 0; a < 4; ++a)
#pragma unroll
                for (int b = 0; b < 8; ++b)
#pragma unroll
                    for (int c = 0; c < 4; ++c) acc[a][b][c] = 0.0f;
        }
    }
}

// ---------------------------------------------------------------------------
// Persistent fp16 1-term GEMM for context: C[M,N] = A[M,K] * B[N,K]^T
// ---------------------------------------------------------------------------
__global__ __launch_bounds__(128, 2)
void gemm_ctx_fp16(const __half* __restrict__ A,
                   const __half* __restrict__ B,
                   float* __restrict__ Cf,
                   int K, int ldC,
                   long long sA, long long sB, long long sC,
                   int ntX, int ntXY, int ntiles)
{
    extern __shared__ __align__(128) char sm[];
    const uint32_t s0 = smem_u32(sm);

    const int bid = (int)blockIdx.x;
    if (bid >= ntiles) return;
    const int gsz = (int)gridDim.x;
    const int nk  = K >> 5;
    const int myN = (ntiles - 1 - bid) / gsz + 1;
    const int total = myN * nk;

    const int tid  = threadIdx.x;
    const int wid  = tid >> 5;
    const int lane = tid & 31;
    const int wm   = wid & 1;
    const int wn   = wid >> 1;

    const int lr0 = tid >> 2;
    const int lc  = tid & 3;

    int lt = bid, lk = 0;
    const __half *lA, *lB;
    auto setLoadTile = [&](int t) {
        int bz = t / ntXY; int rr = t - bz * ntXY;
        int by = rr / ntX; int bx = rr - by * ntX;
        lA = A + (long long)bz * sA + (long long)(by << 7) * K;
        lB = B + (long long)bz * sB + (long long)(bx << 7) * K;
    };
    setLoadTile(lt);

    auto tileLoad = [&](int stage) {
        const uint32_t db = s0 + stage * CTX_STAGE_B;
        const int k0 = lk << 5;
#pragma unroll
        for (int i = 0; i < 4; ++i) {
            const int r = lr0 + i * 32;
            const uint32_t so = sw_addr(r, lc);
            const long long go = (long long)r * K + k0 + lc * 8;
            cp_async16(db + 0 * TILE_B + so, lA + go);
            cp_async16(db + 1 * TILE_B + so, lB + go);
        }
        CP_COMMIT();
        if (++lk == nk) { lk = 0; lt += gsz; if (lt < ntiles) setLoadTile(lt); }
    };

    const int rowA0 = wm * 64 + (lane & 15);
    const int hiA   = lane >> 4;
    const int rowB0 = wn * 64 + (lane & 7) + ((lane & 16) >> 1);
    const int hiB   = (lane & 8) >> 3;

    float acc[4][8][4];
#pragma unroll
    for (int a = 0; a < 4; ++a)
#pragma unroll
        for (int b = 0; b < 8; ++b)
#pragma unroll
            for (int c = 0; c < 4; ++c) acc[a][b][c] = 0.0f;

    tileLoad(0);
    tileLoad(1);

    int cst = 0, lst = 2;
    int ct = bid, ck = 0;

    for (int g = 0; g < total; ++g) {
        if (g + 2 < total) { CP_WAIT1(); } else { CP_WAIT0(); }
        __syncthreads();
        if (g + 2 < total) { tileLoad(lst); lst = (lst == 2) ? 0 : lst + 1; }

        const uint32_t sb = s0 + cst * CTX_STAGE_B;
        cst = (cst == 2) ? 0 : cst + 1;

#pragma unroll
        for (int ks = 0; ks < 2; ++ks) {
            uint32_t fA[4][4];
#pragma unroll
            for (int mt = 0; mt < 4; ++mt) {
                const int r = rowA0 + mt * 16;
                const uint32_t ao = sw_addr(r, hiA + ks * 2);
                ldm_x4(fA[mt], sb + 0 * TILE_B + ao);
            }
#pragma unroll
            for (int pp = 0; pp < 4; ++pp) {
                const int rb = rowB0 + pp * 16;
                const uint32_t bo = sw_addr(rb, hiB + ks * 2);
                uint32_t fB[4];
                ldm_x4(fB, sb + 1 * TILE_B + bo);
#pragma unroll
                for (int q = 0; q < 2; ++q) {
                    const int nt = pp * 2 + q;
#pragma unroll
                    for (int mt = 0; mt < 4; ++mt)
                        mma_fp16(acc[mt][nt], fA[mt], fB + q * 2);
                }
            }
        }

        if (++ck == nk) {
            ck = 0;
            int bz = ct / ntXY; int rr = ct - bz * ntXY;
            int by = rr / ntX;  int bx = rr - by * ntX;
            const int rBase = (by << 7) + wm * 64 + (lane >> 2);
            const int cBase = (bx << 7) + wn * 64 + (lane & 3) * 2;
            const long long zC = (long long)bz * sC;
#pragma unroll
            for (int mt = 0; mt < 4; ++mt) {
#pragma unroll
                for (int h = 0; h < 2; ++h) {
                    const int row = rBase + mt * 16 + h * 8;
#pragma unroll
                    for (int nt = 0; nt < 8; ++nt) {
                        const int col = cBase + nt * 8;
                        float2 fv;
                        fv.x = acc[mt][nt][h * 2 + 0];
                        fv.y = acc[mt][nt][h * 2 + 1];
                        *(float2*)(Cf + zC + (long long)row * ldC + col) = fv;
                    }
                }
            }
            ct += gsz;
#pragma unroll
            for (int a = 0; a < 4; ++a)
#pragma unroll
                for (int b = 0; b < 8; ++b)
#pragma unroll
                    for (int c = 0; c < 4; ++c) acc[a][b][c] = 0.0f;
        }
    }
}

// ---------------------------------------------------------------------------
// Elementwise fp32 -> (hi, lo) bf16 split
// ---------------------------------------------------------------------------
__global__ __launch_bounds__(256)
void convert_split(const float4* __restrict__ in, __nv_bfloat16* __restrict__ oh,
                   __nv_bfloat16* __restrict__ ol, int n4)
{
    __nv_bfloat162* oh2 = reinterpret_cast<__nv_bfloat162*>(oh);
    __nv_bfloat162* ol2 = reinterpret_cast<__nv_bfloat162*>(ol);
    for (int i = blockIdx.x * 256 + threadIdx.x; i < n4; i += gridDim.x * 256) {
        float4 v = in[i];
        __nv_bfloat16 h0, l0, h1, l1, h2, l2, h3, l3;
        split2(v.x, h0, l0); split2(v.y, h1, l1);
        split2(v.z, h2, l2); split2(v.w, h3, l3);
        __nv_bfloat162 a; a.x = h0; a.y = h1;
        __nv_bfloat162 b; b.x = h2; b.y = h3;
        oh2[i * 2] = a; oh2[i * 2 + 1] = b;
        a.x = l0; a.y = l1; b.x = l2; b.y = l3;
        ol2[i * 2] = a; ol2[i * 2 + 1] = b;
    }
}

// ---------------------------------------------------------------------------
// Fused enc prep: row-major bf16 hi/lo AND transposed [D][TK] fp16.
// blockDim (32,8), grid (D/32, TK/32, B)
// ---------------------------------------------------------------------------
__global__ __launch_bounds__(256)
void prep_enc(const float* __restrict__ in,
              __nv_bfloat16* __restrict__ rh, __nv_bfloat16* __restrict__ rl,
              __half* __restrict__ th)
{
    __shared__ float t[32][33];
    const long long zi = (long long)blockIdx.z * TK * D;
    const long long zo = (long long)blockIdx.z * D * TK;
    const int c0 = blockIdx.x * 32, r0 = blockIdx.y * 32;
    const int tx = threadIdx.x, ty0 = threadIdx.y;
#pragma unroll
    for (int i = 0; i < 4; ++i) {
        int ty = ty0 + i * 8;
        float v = in[zi + (long long)(r0 + ty) * D + c0 + tx];
        t[ty][tx] = v;
        __nv_bfloat16 h, l; split2(v, h, l);
        long long o = zi + (long long)(r0 + ty) * D + c0 + tx;
        rh[o] = h; rl[o] = l;
    }
    __syncthreads();
#pragma unroll
    for (int i = 0; i < 4; ++i) {
        int ty = ty0 + i * 8;
        float v = t[tx][ty];                 // = in[r0+tx][c0+ty]
        long long o = zo + (long long)(c0 + ty) * TK + r0 + tx;
        th[o] = __float2half_rn(v);
    }
}

// ---------------------------------------------------------------------------
// Transpose + split (for W): in [R][C] fp32 -> out [C][R] bf16 hi/lo
// ---------------------------------------------------------------------------
__global__ __launch_bounds__(256)
void transpose_split(const float* __restrict__ in, __nv_bfloat16* __restrict__ oh,
                     __nv_bfloat16* __restrict__ ol, int R, int C)
{
    __shared__ float t[32][33];
    const int c0 = blockIdx.x * 32, r0 = blockIdx.y * 32;
    const int tx = threadIdx.x, ty0 = threadIdx.y;
#pragma unroll
    for (int i = 0; i < 4; ++i) {
        int ty = ty0 + i * 8;
        t[ty][tx] = in[(long long)(r0 + ty) * C + c0 + tx];
    }
    __syncthreads();
#pragma unroll
    for (int i = 0; i < 4; ++i) {
        int ty = ty0 + i * 8;
        float v = t[tx][ty];
        __nv_bfloat16 h, l; split2(v, h, l);
        long long o = (long long)(c0 + ty) * R + r0 + tx;
        oh[o] = h; ol[o] = l;
    }
}

// ---------------------------------------------------------------------------
// In-place row softmax over 2048 cols + single fp16 output for context GEMM
// ---------------------------------------------------------------------------
__global__ __launch_bounds__(256)
void softmax2048(float* __restrict__ data, __half* __restrict__ alh)
{
    float* row = data + (long long)blockIdx.x * 2048;
    __half2* hrow = reinterpret_cast<__half2*>(alh + (long long)blockIdx.x * 2048);
    const int tid = threadIdx.x;

    float4 v0 = reinterpret_cast<float4*>(row)[tid];
    float4 v1 = reinterpret_cast<float4*>(row)[tid + 256];

    __shared__ float smr[8];
    __shared__ float bcast;

    float m = fmaxf(fmaxf(fmaxf(v0.x, v0.y), fmaxf(v0.z, v0.w)),
                    fmaxf(fmaxf(v1.x, v1.y), fmaxf(v1.z, v1.w)));
#pragma unroll
    for (int o = 16; o > 0; o >>= 1) m = fmaxf(m, __shfl_xor_sync(0xffffffffu, m, o));
    if ((tid & 31) == 0) smr[tid >> 5] = m;
    __syncthreads();
    if (tid == 0) {
        float t = smr[0];
#pragma unroll
        for (int i = 1; i < 8; ++i) t = fmaxf(t, smr[i]);
        bcast = t;
    }
    __syncthreads();
    m = bcast;
    __syncthreads();

    v0.x = __expf(v0.x - m); v0.y = __expf(v0.y - m);
    v0.z = __expf(v0.z - m); v0.w = __expf(v0.w - m);
    v1.x = __expf(v1.x - m); v1.y = __expf(v1.y - m);
    v1.z = __expf(v1.z - m); v1.w = __expf(v1.w - m);
    float s = (v0.x + v0.y) + (v0.z + v0.w) + (v1.x + v1.y) + (v1.z + v1.w);
#pragma unroll
    for (int o = 16; o > 0; o >>= 1) s += __shfl_xor_sync(0xffffffffu, s, o);
    if ((tid & 31) == 0) smr[tid >> 5] = s;
    __syncthreads();
    if (tid == 0) {
        float t = 0.0f;
#pragma unroll
        for (int i = 0; i < 8; ++i) t += smr[i];
        bcast = 1.0f / t;
    }
    __syncthreads();
    const float r = bcast;

    v0.x *= r; v0.y *= r; v0.z *= r; v0.w *= r;
    v1.x *= r; v1.y *= r; v1.z *= r; v1.w *= r;
    reinterpret_cast<float4*>(row)[tid]       = v0;
    reinterpret_cast<float4*>(row)[tid + 256] = v1;

    hrow[tid * 2]             = __floats2half2_rn(v0.x, v0.y);
    hrow[tid * 2 + 1]         = __floats2half2_rn(v0.z, v0.w);
    hrow[(256 + tid) * 2]     = __floats2half2_rn(v1.x, v1.y);
    hrow[(256 + tid) * 2 + 1] = __floats2half2_rn(v1.z, v1.w);
}

// ---------------------------------------------------------------------------
extern "C" void kernel_launch(void* const* d_in, const int* in_sizes, int n_in,
                              void* d_out, int out_size)
{
    const float* dec = (const float*)d_in[0];   // [B, TQ, D]
    const float* enc = (const float*)d_in[1];   // [B, TK, D]
    const float* Wk  = (const float*)d_in[2];   // [D, D]
    const float* bia = (const float*)d_in[3];   // [D]
    if (n_in >= 4 && in_sizes[2] == D && in_sizes[3] == D * D) {
        const float* t = Wk; Wk = bia; bia = t;
    }

    float* out     = (float*)d_out;
    float* context = out;                          // B*TQ*D
    float* align   = out + (size_t)Bsz * TQ * D;   // B*TQ*TK (score scratch too)

    __nv_bfloat16 *dec_h, *dec_l, *enc_h, *enc_l;
    __half *encT_h, *al_f16;
    __nv_bfloat16 *Wt_h, *Wt_l, *key_h, *key_l;
    cudaGetSymbolAddress((void**)&dec_h,  g_dec_h);
    cudaGetSymbolAddress((void**)&dec_l,  g_dec_l);
    cudaGetSymbolAddress((void**)&enc_h,  g_enc_h);
    cudaGetSymbolAddress((void**)&enc_l,  g_enc_l);
    cudaGetSymbolAddress((void**)&encT_h, g_encT_h);
    cudaGetSymbolAddress((void**)&Wt_h,   g_Wt_h);
    cudaGetSymbolAddress((void**)&Wt_l,   g_Wt_l);
    cudaGetSymbolAddress((void**)&key_h,  g_key_h);
    cudaGetSymbolAddress((void**)&key_l,  g_key_l);
    cudaGetSymbolAddress((void**)&al_f16, g_al_f16);

    cudaFuncSetAttribute(gemm_bf16x3,   cudaFuncAttributeMaxDynamicSharedMemorySize, SMEM_DYN);
    cudaFuncSetAttribute(gemm_ctx_fp16, cudaFuncAttributeMaxDynamicSharedMemorySize, CTX_SMEM);

    // 1) prep
    const int n4 = Bsz * TQ * D / 4;
    convert_split<<<4096, 256>>>((const float4*)dec, dec_h, dec_l, n4);
    prep_enc<<<dim3(D / 32, TK / 32, Bsz), dim3(32, 8)>>>(
        enc, enc_h, enc_l, encT_h);
    transpose_split<<<dim3(D / 32, D / 32, 1), dim3(32, 8)>>>(
        Wk, Wt_h, Wt_l, D, D);

    // 2) keys = enc @ W + bias -> split bf16   (M=32768, N=1024, K=1024)
    {
        const int ntX = D / 128, ntY = (Bsz * TK) / 128, ntB = 1;
        gemm_bf16x3<<<PERSIST_GRID, 128, SMEM_DYN>>>(
            enc_h, enc_l, Wt_h, Wt_l,
            nullptr, key_h, key_l, bia,
            D, D, 0LL, 0LL, 0LL,
            ntX, ntX * ntY, ntX * ntY * ntB);
    }

    // 3) score[b] = dec[b] @ keys[b]^T -> fp32 into align region
    {
        const int ntX = TK / 128, ntY = TQ / 128, ntB = Bsz;
        gemm_bf16x3<<<PERSIST_GRID, 128, SMEM_DYN>>>(
            dec_h, dec_l, key_h, key_l,
            align, nullptr, nullptr, nullptr,
            D, TK, (long long)TQ * D, (long long)TK * D, (long long)TQ * TK,
            ntX, ntX * ntY, ntX * ntY * ntB);
    }

    // 4) softmax (in place) + fp16 alignment for context GEMM
    softmax2048<<<Bsz * TQ, 256>>>(align, al_f16);

    // 5) context[b] = align[b] @ enc[b]   (fp16 1-term, B = encT fp16)
    {
        const int ntX = D / 128, ntY = TQ / 128, ntB = Bsz;
        gemm_ctx_fp16<<<PERSIST_GRID, 128, CTX_SMEM>>>(
            al_f16, encT_h,
            context, TK, D,
            (long long)TQ * TK, (long long)D * TK, (long long)TQ * D,
            ntX, ntX * ntY, ntX * ntY * ntB);
    }
}

// round 15
// speedup vs baseline: 1.0252x; 1.0252x over previous
#include <cuda_runtime.h>
#include <cuda_bf16.h>
#include <cuda_fp16.h>
#include <cstdint>

// LuongAttention B=16, TQ=2048, TK=2048, D=1024
// out = [context (B*TQ*D fp32) | alignment (B*TQ*TK fp32)]
static constexpr int Bsz = 16;
static constexpr int TQ  = 2048;
static constexpr int TK  = 2048;
static constexpr int D   = 1024;

// ---------------- device scratch (allocation-free, 16B aligned) ----------------
__device__ __align__(16) __nv_bfloat16 g_dec_h[(size_t)Bsz * TQ * D];
__device__ __align__(16) __nv_bfloat16 g_dec_l[(size_t)Bsz * TQ * D];
__device__ __align__(16) __nv_bfloat16 g_enc_h[(size_t)Bsz * TK * D];
__device__ __align__(16) __nv_bfloat16 g_enc_l[(size_t)Bsz * TK * D];
__device__ __align__(16) __half        g_encT_h[(size_t)Bsz * D * TK];   // fp16 (single)
__device__ __align__(16) __nv_bfloat16 g_Wt_h[(size_t)D * D];
__device__ __align__(16) __nv_bfloat16 g_Wt_l[(size_t)D * D];
__device__ __align__(16) __nv_bfloat16 g_key_h[(size_t)Bsz * TK * D];
__device__ __align__(16) __nv_bfloat16 g_key_l[(size_t)Bsz * TK * D];
__device__ __align__(16) __half        g_al_f16[(size_t)Bsz * TQ * TK];  // fp16 alignment

// ---------------- helpers ----------------
__device__ __forceinline__ uint32_t smem_u32(const void* p) {
    uint32_t a;
    asm("{ .reg .u64 t; cvta.to.shared.u64 t, %1; cvt.u32.u64 %0, t; }"
        : "=r"(a) : "l"(p));
    return a;
}
__device__ __forceinline__ void cp_async16(uint32_t dst, const void* src) {
    asm volatile("{ .reg .u64 g; cvta.to.global.u64 g, %1;"
                 "  cp.async.cg.shared.global [%0], [g], 16; }"
                 :: "r"(dst), "l"(src) : "memory");
}
#define CP_COMMIT() asm volatile("cp.async.commit_group;" ::: "memory")
#define CP_WAIT1()  asm volatile("cp.async.wait_group 1;" ::: "memory")
#define CP_WAIT0()  asm volatile("cp.async.wait_group 0;" ::: "memory")

__device__ __forceinline__ void ldm_x4(uint32_t* r, uint32_t addr) {
    asm volatile("ldmatrix.sync.aligned.m8n8.x4.shared.b16 {%0,%1,%2,%3}, [%4];"
                 : "=r"(r[0]), "=r"(r[1]), "=r"(r[2]), "=r"(r[3]) : "r"(addr));
}
__device__ __forceinline__ void mma_bf16(float* c, const uint32_t* a, const uint32_t* b) {
    asm volatile("mma.sync.aligned.m16n8k16.row.col.f32.bf16.bf16.f32 "
                 "{%0,%1,%2,%3}, {%4,%5,%6,%7}, {%8,%9}, {%0,%1,%2,%3};"
                 : "+f"(c[0]), "+f"(c[1]), "+f"(c[2]), "+f"(c[3])
                 : "r"(a[0]), "r"(a[1]), "r"(a[2]), "r"(a[3]), "r"(b[0]), "r"(b[1]));
}
__device__ __forceinline__ void mma_fp16(float* c, const uint32_t* a, const uint32_t* b) {
    asm volatile("mma.sync.aligned.m16n8k16.row.col.f32.f16.f16.f32 "
                 "{%0,%1,%2,%3}, {%4,%5,%6,%7}, {%8,%9}, {%0,%1,%2,%3};"
                 : "+f"(c[0]), "+f"(c[1]), "+f"(c[2]), "+f"(c[3])
                 : "r"(a[0]), "r"(a[1]), "r"(a[2]), "r"(a[3]), "r"(b[0]), "r"(b[1]));
}
__device__ __forceinline__ void split2(float x, __nv_bfloat16& h, __nv_bfloat16& l) {
    h = __float2bfloat16_rn(x);
    l = __float2bfloat16_rn(x - __bfloat162float(h));
}

// smem geometry: 128 rows x 64B (32 elems), XOR swizzle -> no padding
static constexpr int TILE_B  = 128 * 64;        // 8192 B per tile array
static constexpr int STAGE_B = 4 * TILE_B;      // Ah,Al,Bh,Bl = 32768 B
static constexpr int NSTAGE  = 3;
static constexpr int SMEM_DYN = NSTAGE * STAGE_B;  // 98304 B

static constexpr int CTX_STAGE_B = 2 * TILE_B;     // A,B = 16384 B
static constexpr int CTX_SMEM    = NSTAGE * CTX_STAGE_B;  // 49152 B

__device__ __forceinline__ uint32_t sw_addr(int row, int chunk) {
    return (uint32_t)(row * 64 + ((chunk ^ ((row >> 1) & 3)) << 4));
}

// ---------------------------------------------------------------------------
// bf16x3 GEMM (emulated fp32) on mma.sync:  C[M,N] = A[M,K] * B[N,K]^T
// Tile 128x128, BK=32, 128 thr (4 warps, 2Mx2N, warp tile 64x64)
// 3-stage cp.async pipeline; TERM-OUTER MMA order: all 32 hh MMAs, then 32 hl,
// then 32 lh -> accumulator RAW chain distance 32 (was 4).
// grid = (N/128, M/128, batch)
// ---------------------------------------------------------------------------
__global__ __launch_bounds__(128, 2)
void gemm_bf16x3(const __nv_bfloat16* __restrict__ Ah, const __nv_bfloat16* __restrict__ Al,
                 const __nv_bfloat16* __restrict__ Bh, const __nv_bfloat16* __restrict__ Bl,
                 float* __restrict__ Cf,
                 __nv_bfloat16* __restrict__ Chi, __nv_bfloat16* __restrict__ Clo,
                 const float* __restrict__ bias,
                 int K, int ldC,
                 long long sA, long long sB, long long sC)
{
    extern __shared__ __align__(128) char sm[];
    const uint32_t s0 = smem_u32(sm);

    const int tid  = threadIdx.x;
    const int wid  = tid >> 5;
    const int lane = tid & 31;
    const int wm   = wid & 1;
    const int wn   = wid >> 1;

    const long long zA = (long long)blockIdx.z * sA;
    const long long zB = (long long)blockIdx.z * sB;
    const __nv_bfloat16* pAh = Ah + zA + (long long)(blockIdx.y * 128) * K;
    const __nv_bfloat16* pAl = Al + zA + (long long)(blockIdx.y * 128) * K;
    const __nv_bfloat16* pBh = Bh + zB + (long long)(blockIdx.x * 128) * K;
    const __nv_bfloat16* pBl = Bl + zB + (long long)(blockIdx.x * 128) * K;

    const int lr0 = tid >> 2;
    const int lc  = tid & 3;
    auto tileLoad = [&](int stage, int k0) {
        const uint32_t db = s0 + stage * STAGE_B;
#pragma unroll
        for (int i = 0; i < 4; ++i) {
            const int r = lr0 + i * 32;
            const uint32_t so = sw_addr(r, lc);
            const long long go = (long long)r * K + k0 + lc * 8;
            cp_async16(db + 0 * TILE_B + so, pAh + go);
            cp_async16(db + 1 * TILE_B + so, pAl + go);
            cp_async16(db + 2 * TILE_B + so, pBh + go);
            cp_async16(db + 3 * TILE_B + so, pBl + go);
        }
        CP_COMMIT();
    };

    const int rowA0 = wm * 64 + (lane & 15);
    const int hiA   = lane >> 4;
    const int rowB0 = wn * 64 + (lane & 7) + ((lane & 16) >> 1);
    const int hiB   = (lane & 8) >> 3;

    float acc[4][8][4];
#pragma unroll
    for (int a = 0; a < 4; ++a)
#pragma unroll
        for (int b = 0; b < 8; ++b)
#pragma unroll
            for (int c = 0; c < 4; ++c) acc[a][b][c] = 0.0f;

    const int nk = K >> 5;
    tileLoad(0, 0);
    tileLoad(1, 32);

    int stage = 0;
    for (int it = 0; it < nk; ++it) {
        if (it + 2 < nk) { CP_WAIT1(); } else { CP_WAIT0(); }
        __syncthreads();
        if (it + 2 < nk) {
            int ns = stage + 2; if (ns >= NSTAGE) ns -= NSTAGE;
            tileLoad(ns, (it + 2) << 5);
        }

        const uint32_t sb = s0 + stage * STAGE_B;
#pragma unroll
        for (int ks = 0; ks < 2; ++ks) {
            // ---- all 16 fragments for this ks-step up front ----
            uint32_t fAh[4][4], fAl[4][4], fBh[4][4], fBl[4][4];
#pragma unroll
            for (int mt = 0; mt < 4; ++mt) {
                const int r = rowA0 + mt * 16;
                const uint32_t ao = sw_addr(r, hiA + ks * 2);
                ldm_x4(fAh[mt], sb + 0 * TILE_B + ao);
                ldm_x4(fAl[mt], sb + 1 * TILE_B + ao);
            }
#pragma unroll
            for (int pp = 0; pp < 4; ++pp) {
                const int rb = rowB0 + pp * 16;
                const uint32_t bo = sw_addr(rb, hiB + ks * 2);
                ldm_x4(fBh[pp], sb + 2 * TILE_B + bo);
                ldm_x4(fBl[pp], sb + 3 * TILE_B + bo);
            }
            // ---- TERM-OUTER: 32 hh, 32 hl, 32 lh (RAW distance 32) ----
#pragma unroll
            for (int pp = 0; pp < 4; ++pp)
#pragma unroll
                for (int q = 0; q < 2; ++q)
#pragma unroll
                    for (int mt = 0; mt < 4; ++mt)
                        mma_bf16(acc[mt][pp * 2 + q], fAh[mt], fBh[pp] + q * 2);
#pragma unroll
            for (int pp = 0; pp < 4; ++pp)
#pragma unroll
                for (int q = 0; q < 2; ++q)
#pragma unroll
                    for (int mt = 0; mt < 4; ++mt)
                        mma_bf16(acc[mt][pp * 2 + q], fAh[mt], fBl[pp] + q * 2);
#pragma unroll
            for (int pp = 0; pp < 4; ++pp)
#pragma unroll
                for (int q = 0; q < 2; ++q)
#pragma unroll
                    for (int mt = 0; mt < 4; ++mt)
                        mma_bf16(acc[mt][pp * 2 + q], fAl[mt], fBh[pp] + q * 2);
        }
        if (++stage >= NSTAGE) stage = 0;
    }

    // ---------------- epilogue ----------------
    const int rBase = blockIdx.y * 128 + wm * 64 + (lane >> 2);
    const int cBase = blockIdx.x * 128 + wn * 64 + (lane & 3) * 2;
    const long long zC = (long long)blockIdx.z * sC;

#pragma unroll
    for (int mt = 0; mt < 4; ++mt) {
#pragma unroll
        for (int h = 0; h < 2; ++h) {
            const int row = rBase + mt * 16 + h * 8;
#pragma unroll
            for (int nt = 0; nt < 8; ++nt) {
                const int col = cBase + nt * 8;
                float v0 = acc[mt][nt][h * 2 + 0];
                float v1 = acc[mt][nt][h * 2 + 1];
                if (bias) { v0 += bias[col]; v1 += bias[col + 1]; }
                const long long o = zC + (long long)row * ldC + col;
                if (Cf) {
                    float2 fv; fv.x = v0; fv.y = v1;
                    *(float2*)(Cf + o) = fv;
                }
                if (Chi) {
                    __nv_bfloat16 h0, l0, h1, l1;
                    split2(v0, h0, l0); split2(v1, h1, l1);
                    __nv_bfloat162 hv; hv.x = h0; hv.y = h1;
                    __nv_bfloat162 lv; lv.x = l0; lv.y = l1;
                    *(__nv_bfloat162*)(Chi + o) = hv;
                    *(__nv_bfloat162*)(Clo + o) = lv;
                }
            }
        }
    }
}

// ---------------------------------------------------------------------------
// fp16 1-term GEMM for context: C[M,N] = A[M,K] * B[N,K]^T
// A fp16 alignment, B fp16 enc. (1 term -> RAW distance already 64)
// ---------------------------------------------------------------------------
__global__ __launch_bounds__(128, 2)
void gemm_ctx_fp16(const __half* __restrict__ A,
                   const __half* __restrict__ B,
                   float* __restrict__ Cf,
                   int K, int ldC,
                   long long sA, long long sB, long long sC)
{
    extern __shared__ __align__(128) char sm[];
    const uint32_t s0 = smem_u32(sm);

    const int tid  = threadIdx.x;
    const int wid  = tid >> 5;
    const int lane = tid & 31;
    const int wm   = wid & 1;
    const int wn   = wid >> 1;

    const long long zA = (long long)blockIdx.z * sA;
    const long long zB = (long long)blockIdx.z * sB;
    const __half* pA = A + zA + (long long)(blockIdx.y * 128) * K;
    const __half* pB = B + zB + (long long)(blockIdx.x * 128) * K;

    const int lr0 = tid >> 2;
    const int lc  = tid & 3;
    auto tileLoad = [&](int stage, int k0) {
        const uint32_t db = s0 + stage * CTX_STAGE_B;
#pragma unroll
        for (int i = 0; i < 4; ++i) {
            const int r = lr0 + i * 32;
            const uint32_t so = sw_addr(r, lc);
            const long long go = (long long)r * K + k0 + lc * 8;
            cp_async16(db + 0 * TILE_B + so, pA + go);
            cp_async16(db + 1 * TILE_B + so, pB + go);
        }
        CP_COMMIT();
    };

    const int rowA0 = wm * 64 + (lane & 15);
    const int hiA   = lane >> 4;
    const int rowB0 = wn * 64 + (lane & 7) + ((lane & 16) >> 1);
    const int hiB   = (lane & 8) >> 3;

    float acc[4][8][4];
#pragma unroll
    for (int a = 0; a < 4; ++a)
#pragma unroll
        for (int b = 0; b < 8; ++b)
#pragma unroll
            for (int c = 0; c < 4; ++c) acc[a][b][c] = 0.0f;

    const int nk = K >> 5;
    tileLoad(0, 0);
    tileLoad(1, 32);

    int stage = 0;
    for (int it = 0; it < nk; ++it) {
        if (it + 2 < nk) { CP_WAIT1(); } else { CP_WAIT0(); }
        __syncthreads();
        if (it + 2 < nk) {
            int ns = stage + 2; if (ns >= NSTAGE) ns -= NSTAGE;
            tileLoad(ns, (it + 2) << 5);
        }

        const uint32_t sb = s0 + stage * CTX_STAGE_B;
#pragma unroll
        for (int ks = 0; ks < 2; ++ks) {
            uint32_t fA[4][4], fB[4][4];
#pragma unroll
            for (int mt = 0; mt < 4; ++mt) {
                const int r = rowA0 + mt * 16;
                const uint32_t ao = sw_addr(r, hiA + ks * 2);
                ldm_x4(fA[mt], sb + 0 * TILE_B + ao);
            }
#pragma unroll
            for (int pp = 0; pp < 4; ++pp) {
                const int rb = rowB0 + pp * 16;
                const uint32_t bo = sw_addr(rb, hiB + ks * 2);
                ldm_x4(fB[pp], sb + 1 * TILE_B + bo);
            }
#pragma unroll
            for (int pp = 0; pp < 4; ++pp)
#pragma unroll
                for (int q = 0; q < 2; ++q)
#pragma unroll
                    for (int mt = 0; mt < 4; ++mt)
                        mma_fp16(acc[mt][pp * 2 + q], fA[mt], fB[pp] + q * 2);
        }
        if (++stage >= NSTAGE) stage = 0;
    }

    // ---------------- epilogue ----------------
    const int rBase = blockIdx.y * 128 + wm * 64 + (lane >> 2);
    const int cBase = blockIdx.x * 128 + wn * 64 + (lane & 3) * 2;
    const long long zC = (long long)blockIdx.z * sC;

#pragma unroll
    for (int mt = 0; mt < 4; ++mt) {
#pragma unroll
        for (int h = 0; h < 2; ++h) {
            const int row = rBase + mt * 16 + h * 8;
#pragma unroll
            for (int nt = 0; nt < 8; ++nt) {
                const int col = cBase + nt * 8;
                float2 fv;
                fv.x = acc[mt][nt][h * 2 + 0];
                fv.y = acc[mt][nt][h * 2 + 1];
                *(float2*)(Cf + zC + (long long)row * ldC + col) = fv;
            }
        }
    }
}

// ---------------------------------------------------------------------------
// Elementwise fp32 -> (hi, lo) bf16 split
// ---------------------------------------------------------------------------
__global__ __launch_bounds__(256)
void convert_split(const float4* __restrict__ in, __nv_bfloat16* __restrict__ oh,
                   __nv_bfloat16* __restrict__ ol, int n4)
{
    __nv_bfloat162* oh2 = reinterpret_cast<__nv_bfloat162*>(oh);
    __nv_bfloat162* ol2 = reinterpret_cast<__nv_bfloat162*>(ol);
    for (int i = blockIdx.x * 256 + threadIdx.x; i < n4; i += gridDim.x * 256) {
        float4 v = in[i];
        __nv_bfloat16 h0, l0, h1, l1, h2, l2, h3, l3;
        split2(v.x, h0, l0); split2(v.y, h1, l1);
        split2(v.z, h2, l2); split2(v.w, h3, l3);
        __nv_bfloat162 a; a.x = h0; a.y = h1;
        __nv_bfloat162 b; b.x = h2; b.y = h3;
        oh2[i * 2] = a; oh2[i * 2 + 1] = b;
        a.x = l0; a.y = l1; b.x = l2; b.y = l3;
        ol2[i * 2] = a; ol2[i * 2 + 1] = b;
    }
}

// ---------------------------------------------------------------------------
// Fused enc prep: row-major bf16 hi/lo AND transposed [D][TK] fp16.
// blockDim (32,8), grid (D/32, TK/32, B)
// ---------------------------------------------------------------------------
__global__ __launch_bounds__(256)
void prep_enc(const float* __restrict__ in,
              __nv_bfloat16* __restrict__ rh, __nv_bfloat16* __restrict__ rl,
              __half* __restrict__ th)
{
    __shared__ float t[32][33];
    const long long zi = (long long)blockIdx.z * TK * D;
    const long long zo = (long long)blockIdx.z * D * TK;
    const int c0 = blockIdx.x * 32, r0 = blockIdx.y * 32;
    const int tx = threadIdx.x, ty0 = threadIdx.y;
#pragma unroll
    for (int i = 0; i < 4; ++i) {
        int ty = ty0 + i * 8;
        float v = in[zi + (long long)(r0 + ty) * D + c0 + tx];
        t[ty][tx] = v;
        __nv_bfloat16 h, l; split2(v, h, l);
        long long o = zi + (long long)(r0 + ty) * D + c0 + tx;
        rh[o] = h; rl[o] = l;
    }
    __syncthreads();
#pragma unroll
    for (int i = 0; i < 4; ++i) {
        int ty = ty0 + i * 8;
        float v = t[tx][ty];                 // = in[r0+tx][c0+ty]
        long long o = zo + (long long)(c0 + ty) * TK + r0 + tx;
        th[o] = __float2half_rn(v);
    }
}

// ---------------------------------------------------------------------------
// Transpose + split (for W): in [R][C] fp32 -> out [C][R] bf16 hi/lo
// ---------------------------------------------------------------------------
__global__ __launch_bounds__(256)
void transpose_split(const float* __restrict__ in, __nv_bfloat16* __restrict__ oh,
                     __nv_bfloat16* __restrict__ ol, int R, int C)
{
    __shared__ float t[32][33];
    const int c0 = blockIdx.x * 32, r0 = blockIdx.y * 32;
    const int tx = threadIdx.x, ty0 = threadIdx.y;
#pragma unroll
    for (int i = 0; i < 4; ++i) {
        int ty = ty0 + i * 8;
        t[ty][tx] = in[(long long)(r0 + ty) * C + c0 + tx];
    }
    __syncthreads();
#pragma unroll
    for (int i = 0; i < 4; ++i) {
        int ty = ty0 + i * 8;
        float v = t[tx][ty];
        __nv_bfloat16 h, l; split2(v, h, l);
        long long o = (long long)(c0 + ty) * R + r0 + tx;
        oh[o] = h; ol[o] = l;
    }
}

// ---------------------------------------------------------------------------
// In-place row softmax over 2048 cols + single fp16 output for context GEMM
// ---------------------------------------------------------------------------
__global__ __launch_bounds__(256)
void softmax2048(float* __restrict__ data, __half* __restrict__ alh)
{
    float* row = data + (long long)blockIdx.x * 2048;
    __half2* hrow = reinterpret_cast<__half2*>(alh + (long long)blockIdx.x * 2048);
    const int tid = threadIdx.x;

    float4 v0 = reinterpret_cast<float4*>(row)[tid];
    float4 v1 = reinterpret_cast<float4*>(row)[tid + 256];

    __shared__ float smr[8];
    __shared__ float bcast;

    float m = fmaxf(fmaxf(fmaxf(v0.x, v0.y), fmaxf(v0.z, v0.w)),
                    fmaxf(fmaxf(v1.x, v1.y), fmaxf(v1.z, v1.w)));
#pragma unroll
    for (int o = 16; o > 0; o >>= 1) m = fmaxf(m, __shfl_xor_sync(0xffffffffu, m, o));
    if ((tid & 31) == 0) smr[tid >> 5] = m;
    __syncthreads();
    if (tid == 0) {
        float t = smr[0];
#pragma unroll
        for (int i = 1; i < 8; ++i) t = fmaxf(t, smr[i]);
        bcast = t;
    }
    __syncthreads();
    m = bcast;
    __syncthreads();

    v0.x = __expf(v0.x - m); v0.y = __expf(v0.y - m);
    v0.z = __expf(v0.z - m); v0.w = __expf(v0.w - m);
    v1.x = __expf(v1.x - m); v1.y = __expf(v1.y - m);
    v1.z = __expf(v1.z - m); v1.w = __expf(v1.w - m);
    float s = (v0.x + v0.y) + (v0.z + v0.w) + (v1.x + v1.y) + (v1.z + v1.w);
#pragma unroll
    for (int o = 16; o > 0; o >>= 1) s += __shfl_xor_sync(0xffffffffu, s, o);
    if ((tid & 31) == 0) smr[tid >> 5] = s;
    __syncthreads();
    if (tid == 0) {
        float t = 0.0f;
#pragma unroll
        for (int i = 0; i < 8; ++i) t += smr[i];
        bcast = 1.0f / t;
    }
    __syncthreads();
    const float r = bcast;

    v0.x *= r; v0.y *= r; v0.z *= r; v0.w *= r;
    v1.x *= r; v1.y *= r; v1.z *= r; v1.w *= r;
    reinterpret_cast<float4*>(row)[tid]       = v0;
    reinterpret_cast<float4*>(row)[tid + 256] = v1;

    hrow[tid * 2]             = __floats2half2_rn(v0.x, v0.y);
    hrow[tid * 2 + 1]         = __floats2half2_rn(v0.z, v0.w);
    hrow[(256 + tid) * 2]     = __floats2half2_rn(v1.x, v1.y);
    hrow[(256 + tid) * 2 + 1] = __floats2half2_rn(v1.z, v1.w);
}

// ---------------------------------------------------------------------------
extern "C" void kernel_launch(void* const* d_in, const int* in_sizes, int n_in,
                              void* d_out, int out_size)
{
    const float* dec = (const float*)d_in[0];   // [B, TQ, D]
    const float* enc = (const float*)d_in[1];   // [B, TK, D]
    const float* Wk  = (const float*)d_in[2];   // [D, D]
    const float* bia = (const float*)d_in[3];   // [D]
    if (n_in >= 4 && in_sizes[2] == D && in_sizes[3] == D * D) {
        const float* t = Wk; Wk = bia; bia = t;
    }

    float* out     = (float*)d_out;
    float* context = out;                          // B*TQ*D
    float* align   = out + (size_t)Bsz * TQ * D;   // B*TQ*TK (score scratch too)

    __nv_bfloat16 *dec_h, *dec_l, *enc_h, *enc_l;
    __half *encT_h, *al_f16;
    __nv_bfloat16 *Wt_h, *Wt_l, *key_h, *key_l;
    cudaGetSymbolAddress((void**)&dec_h,  g_dec_h);
    cudaGetSymbolAddress((void**)&dec_l,  g_dec_l);
    cudaGetSymbolAddress((void**)&enc_h,  g_enc_h);
    cudaGetSymbolAddress((void**)&enc_l,  g_enc_l);
    cudaGetSymbolAddress((void**)&encT_h, g_encT_h);
    cudaGetSymbolAddress((void**)&Wt_h,   g_Wt_h);
    cudaGetSymbolAddress((void**)&Wt_l,   g_Wt_l);
    cudaGetSymbolAddress((void**)&key_h,  g_key_h);
    cudaGetSymbolAddress((void**)&key_l,  g_key_l);
    cudaGetSymbolAddress((void**)&al_f16, g_al_f16);

    cudaFuncSetAttribute(gemm_bf16x3,   cudaFuncAttributeMaxDynamicSharedMemorySize, SMEM_DYN);
    cudaFuncSetAttribute(gemm_ctx_fp16, cudaFuncAttributeMaxDynamicSharedMemorySize, CTX_SMEM);

    // 1) prep
    const int n4 = Bsz * TQ * D / 4;
    convert_split<<<4096, 256>>>((const float4*)dec, dec_h, dec_l, n4);
    prep_enc<<<dim3(D / 32, TK / 32, Bsz), dim3(32, 8)>>>(
        enc, enc_h, enc_l, encT_h);
    transpose_split<<<dim3(D / 32, D / 32, 1), dim3(32, 8)>>>(
        Wk, Wt_h, Wt_l, D, D);

    // 2) keys = enc @ W + bias -> split bf16   (M=32768, N=1024, K=1024)
    gemm_bf16x3<<<dim3(D / 128, (Bsz * TK) / 128, 1), 128, SMEM_DYN>>>(
        enc_h, enc_l, Wt_h, Wt_l,
        nullptr, key_h, key_l, bia,
        D, D, 0LL, 0LL, 0LL);

    // 3) score[b] = dec[b] @ keys[b]^T -> fp32 into align region
    gemm_bf16x3<<<dim3(TK / 128, TQ / 128, Bsz), 128, SMEM_DYN>>>(
        dec_h, dec_l, key_h, key_l,
        align, nullptr, nullptr, nullptr,
        D, TK, (long long)TQ * D, (long long)TK * D, (long long)TQ * TK);

    // 4) softmax (in place) + fp16 alignment for context GEMM
    softmax2048<<<Bsz * TQ, 256>>>(align, al_f16);

    // 5) context[b] = align[b] @ enc[b]   (fp16 1-term, B = encT fp16)
    gemm_ctx_fp16<<<dim3(D / 128, TQ / 128, Bsz), 128, CTX_SMEM>>>(
        al_f16, encT_h,
        context, TK, D,
        (long long)TQ * TK, (long long)D * TK, (long long)TQ * D);
}